// round 7
// baseline (speedup 1.0000x reference)
#include <cuda_runtime.h>
#include <math.h>

// Problem constants
#define D   784
#define H   500
#define HP  512
#define B   512
#define S   28           // segments (784 = 28*28)
#define L   28           // steps per segment
#define BD  (B*D)
#define CHS 7            // steps per chunk in k_scan
#define NCH 4            // chunks (4*7 = 28)

typedef unsigned long long u64;

// Static device scratch
__device__ float g_WT[D*HP];     // W^T padded: [d][h]
__device__ float g_Vp[D*HP];     // V padded:   [d][h]
__device__ float g_c [HP];
__device__ float g_A [B*S*HP];   // partials then checkpoints: [b][s][h]

// ---- packed f32x2 helpers -------------------------------------------------
__device__ __forceinline__ u64 ffma2(u64 a, u64 b, u64 c) {
    u64 d;
    asm("fma.rn.f32x2 %0, %1, %2, %3;" : "=l"(d) : "l"(a), "l"(b), "l"(c));
    return d;
}
__device__ __forceinline__ u64 add2(u64 a, u64 b) {
    u64 d;
    asm("add.rn.f32x2 %0, %1, %2;" : "=l"(d) : "l"(a), "l"(b));
    return d;
}
__device__ __forceinline__ u64 relu2(u64 a) {
    u64 r;
    asm("{\n\t.reg .f32 lo, hi;\n\t"
        "mov.b64 {lo, hi}, %1;\n\t"
        "max.f32 lo, lo, 0f00000000;\n\t"
        "max.f32 hi, hi, 0f00000000;\n\t"
        "mov.b64 %0, {lo, hi};\n\t}" : "=l"(r) : "l"(a));
    return r;
}
__device__ __forceinline__ u64 pack2(float x) {
    u64 r;
    asm("mov.b64 %0, {%1, %1};" : "=l"(r) : "f"(x));
    return r;
}
__device__ __forceinline__ float hadd2(u64 a) {
    float lo, hi;
    asm("mov.b64 {%0, %1}, %2;" : "=f"(lo), "=f"(hi) : "l"(a));
    return lo + hi;
}

// ---------------------------------------------------------------------------
// K0a: pad V rows 500->512, pad c.
// ---------------------------------------------------------------------------
__global__ void k_packV(const float* __restrict__ V,
                        const float* __restrict__ c) {
    int d = blockIdx.x;
    int t = threadIdx.x;
    g_Vp[d*HP + t] = (t < H) ? V[d*H + t] : 0.0f;
    if (d == 0) g_c[t] = (t < H) ? c[t] : 0.0f;
}

// ---------------------------------------------------------------------------
// K0b: tiled transpose W [H,D] -> g_WT [D,HP].
// ---------------------------------------------------------------------------
__global__ void k_packW(const float* __restrict__ W) {
    __shared__ float tile[32][33];
    int d0 = blockIdx.x * 32;
    int h0 = blockIdx.y * 32;
    int tx = threadIdx.x;
    int ty = threadIdx.y;
    #pragma unroll
    for (int i = 0; i < 4; i++) {
        int h = h0 + ty + 8*i;
        int d = d0 + tx;
        float v = 0.0f;
        if (h < H && d < D) v = W[h*D + d];
        tile[ty + 8*i][tx] = v;
    }
    __syncthreads();
    #pragma unroll
    for (int i = 0; i < 4; i++) {
        int d = d0 + ty + 8*i;
        int h = h0 + tx;
        if (d < D) g_WT[d*HP + h] = tile[tx][ty + 8*i];
    }
}

// ---------------------------------------------------------------------------
// K1: partial GEMM. P_s[rows,:] = X[rows, sL:(s+1)L] @ W[sL:(s+1)L, :]
//     Stored at g_A[row][s][:]  (layout [b][s][h]).
// ---------------------------------------------------------------------------
__global__ __launch_bounds__(256)
void k_partial(const float* __restrict__ x) {
    int s  = blockIdx.x;         // 0..26
    int rb = blockIdx.y;         // 0..15
    int t  = threadIdx.x;        // h-pair index
    int rowbase = rb * 32;

    __shared__ u64 sxp[32 * L];
    for (int i = t; i < 32 * L; i += 256) {
        int r = i / L, j = i - r * L;
        sxp[i] = pack2(x[(rowbase + r)*D + s*L + j]);
    }
    __syncthreads();

    u64 acc[32];
    #pragma unroll
    for (int r = 0; r < 32; r++) acc[r] = 0ull;

    const u64* W1 = (const u64*)g_WT;
    #pragma unroll 2
    for (int j = 0; j < L; j++) {
        u64 wv = W1[(size_t)(s*L + j)*256 + t];
        #pragma unroll
        for (int r = 0; r < 32; r++)
            acc[r] = ffma2(sxp[r*L + j], wv, acc[r]);
    }

    u64* A1 = (u64*)g_A;
    #pragma unroll
    for (int r = 0; r < 32; r++)
        A1[((size_t)(rowbase + r)*S + s)*256 + t] = acc[r];
}

// ---------------------------------------------------------------------------
// K2: prefix over segments, one thread per (b,h), in place.
// ---------------------------------------------------------------------------
__global__ __launch_bounds__(256)
void k_prefix() {
    int g = blockIdx.x * 256 + threadIdx.x;
    int h = g & (HP - 1);
    int b = g >> 9;
    float v = g_c[h];
    float* base = g_A + (size_t)b*S*HP + h;
    #pragma unroll
    for (int s = 0; s < S; s++) {
        float p = base[s*HP];
        base[s*HP] = v;
        v += p;
    }
}

// ---------------------------------------------------------------------------
// K3: scan, lane=row layout. Block = (segment s, 32-row tile).
// Warp w owns h in [64w, 64w+64); lane = row; state = 32 u64 regs/lane.
// V/W staged per 7-step chunk in smem (LDS.128 broadcast); dot completes
// in-lane (no shuffles); cross-warp combine + epilogue deferred per chunk.
// ---------------------------------------------------------------------------
__global__ __launch_bounds__(256, 2)
void k_scan(const float* __restrict__ x,
            const float* __restrict__ u,
            const float* __restrict__ bvec,
            float* __restrict__ out) {
    int s    = blockIdx.x;       // 0..27
    int rb   = blockIdx.y;       // 0..15
    int tid  = threadIdx.x;
    int w    = tid >> 5;
    int lane = tid & 31;
    int rowbase = rb * 32;

    __shared__ __align__(16) float svw[CHS*8*128];  // [jj][w][V 64 | W 64]
    __shared__ float part[8*32*9];                  // [w][row], stride 9
    __shared__ float sx  [32*29];
    __shared__ float sb  [L];
    __shared__ float sl  [32*L];
    __shared__ float sxs [32*L];

    // State init: lane = row, slice [64w, 64w+64).
    u64 a[32];
    {
        const ulonglong2* A2 = (const ulonglong2*)
            (g_A + ((size_t)(rowbase + lane)*S + s)*HP + w*64);
        #pragma unroll
        for (int i = 0; i < 16; i++) {
            ulonglong2 q = A2[i];
            a[2*i] = q.x; a[2*i+1] = q.y;
        }
    }

    for (int i = tid; i < 32*L; i += 256) {
        int r = i / L, j = i - r*L;
        sx[r*29 + j] = x[(size_t)(rowbase + r)*D + s*L + j];
    }
    if (tid < L) sb[tid] = bvec[s*L + tid];

    // Stage chunk 0.
    float4 st[CHS];
    {
        int dbase = s*L;
        #pragma unroll
        for (int k = 0; k < CHS; k++) {
            int f = tid + k*256;
            int q = f & 15;
            int gg = f >> 4;
            int which = gg & 1;
            int gw = gg >> 1;
            int w2 = gw & 7;
            int jj = gw >> 3;
            const float* src = which ? g_WT : g_Vp;
            st[k] = *(const float4*)(src + (size_t)(dbase + jj)*HP + w2*64 + q*4);
        }
        #pragma unroll
        for (int k = 0; k < CHS; k++)
            ((float4*)svw)[tid + k*256] = st[k];
    }
    __syncthreads();

    for (int c = 0; c < NCH; c++) {
        // Prefetch next chunk into registers (overlaps with compute).
        if (c < NCH-1) {
            int dbase = s*L + (c+1)*CHS;
            #pragma unroll
            for (int k = 0; k < CHS; k++) {
                int f = tid + k*256;
                int q = f & 15;
                int gg = f >> 4;
                int which = gg & 1;
                int gw = gg >> 1;
                int w2 = gw & 7;
                int jj = gw >> 3;
                const float* src = which ? g_WT : g_Vp;
                st[k] = *(const float4*)(src + (size_t)(dbase + jj)*HP + w2*64 + q*4);
            }
        }

        // Compute 7 steps.
        for (int jj = 0; jj < CHS; jj++) {
            int j = c*CHS + jj;
            u64 xx = pack2(sx[lane*29 + j]);
            const ulonglong2* Vb = (const ulonglong2*)(svw + (jj*8 + w)*128);
            const ulonglong2* Wb = Vb + 16;   // +64 floats
            u64 dp0 = 0ull, dp1 = 0ull;
            #pragma unroll
            for (int i = 0; i < 16; i++) {
                ulonglong2 vq = Vb[i];
                ulonglong2 wq = Wb[i];
                dp0 = ffma2(relu2(a[2*i  ]), vq.x, dp0);
                dp1 = ffma2(relu2(a[2*i+1]), vq.y, dp1);
                a[2*i  ] = ffma2(xx, wq.x, a[2*i  ]);
                a[2*i+1] = ffma2(xx, wq.y, a[2*i+1]);
            }
            part[(w*32 + lane)*9 + jj] = hadd2(add2(dp0, dp1));
        }

        __syncthreads();   // part complete, svw consumed

        if (c < NCH-1) {
            #pragma unroll
            for (int k = 0; k < CHS; k++)
                ((float4*)svw)[tid + k*256] = st[k];
        }

        // Reduce across warps + epilogue for this chunk.
        if (tid < 32*CHS) {
            int row = tid & 31, jj = tid >> 5;
            float sum = 0.0f;
            #pragma unroll
            for (int w2 = 0; w2 < 8; w2++)
                sum += part[(w2*32 + row)*9 + jj];
            int j = c*CHS + jj;
            float lv = sum + sb[j];
            float uu = u[(size_t)(rowbase + row)*D + s*L + j];
            float e  = expf(-lv);
            float xs = (fmaf(uu, e, uu) < 1.0f) ? 1.0f : 0.0f;
            sl [row*L + j] = lv;
            sxs[row*L + j] = xs;
        }
        __syncthreads();   // part free, svw(c+1) visible
    }

    // Coalesced flush.
    for (int i = tid; i < 32*L; i += 256) {
        int r = i / L, j = i - r*L;
        size_t g = (size_t)(rowbase + r)*D + s*L + j;
        out[g]      = sl[i];
        out[BD + g] = sxs[i];
    }
}

// ---------------------------------------------------------------------------
// Inputs: x[B,D], u[B,D], W[H,D], c[H], V[D,H], b[D]
// Output: [ l (B*D) | x_sample (B*D) ]
// ---------------------------------------------------------------------------
extern "C" void kernel_launch(void* const* d_in, const int* in_sizes, int n_in,
                              void* d_out, int out_size) {
    (void)in_sizes; (void)n_in; (void)out_size;
    const float* x    = (const float*)d_in[0];
    const float* u    = (const float*)d_in[1];
    const float* W    = (const float*)d_in[2];
    const float* c    = (const float*)d_in[3];
    const float* V    = (const float*)d_in[4];
    const float* bvec = (const float*)d_in[5];
    float* out = (float*)d_out;

    k_packV  <<<D, HP>>>(V, c);
    k_packW  <<<dim3((D+31)/32, HP/32), dim3(32, 8)>>>(W);
    k_partial<<<dim3(S-1, B/32), 256>>>(x);
    k_prefix <<<(B*HP)/256, 256>>>();
    k_scan   <<<dim3(S, B/32), 256>>>(x, u, bvec, out);
}

// round 10
// speedup vs baseline: 1.0433x; 1.0433x over previous
#include <cuda_runtime.h>
#include <cstdint>
#include <math.h>

// Problem constants
#define D   784
#define H   500
#define HP  512
#define B   512
#define S   28           // segments (784 = 28*28)
#define L   28           // steps per segment
#define BD  (B*D)
#define CHS 7            // steps per chunk in k_scan
#define NCH 4            // chunks (4*7 = 28)

typedef unsigned long long u64;
typedef unsigned int u32;

// Static device scratch
__device__ float g_WT[D*HP];     // W^T padded: [d][h]
__device__ float g_Vp[D*HP];     // V padded:   [d][h]
__device__ float g_c [HP];
__device__ float g_A [B*S*HP];   // partials then checkpoints: [b][s][h]

// ---- packed f32x2 helpers -------------------------------------------------
__device__ __forceinline__ u64 ffma2(u64 a, u64 b, u64 c) {
    u64 d;
    asm("fma.rn.f32x2 %0, %1, %2, %3;" : "=l"(d) : "l"(a), "l"(b), "l"(c));
    return d;
}
__device__ __forceinline__ u64 add2(u64 a, u64 b) {
    u64 d;
    asm("add.rn.f32x2 %0, %1, %2;" : "=l"(d) : "l"(a), "l"(b));
    return d;
}
__device__ __forceinline__ u64 relu2(u64 a) {
    u64 r;
    asm("{\n\t.reg .f32 lo, hi;\n\t"
        "mov.b64 {lo, hi}, %1;\n\t"
        "max.f32 lo, lo, 0f00000000;\n\t"
        "max.f32 hi, hi, 0f00000000;\n\t"
        "mov.b64 %0, {lo, hi};\n\t}" : "=l"(r) : "l"(a));
    return r;
}
__device__ __forceinline__ u64 pack2(float x) {
    u64 r;
    asm("mov.b64 %0, {%1, %1};" : "=l"(r) : "f"(x));
    return r;
}
__device__ __forceinline__ float hadd2(u64 a) {
    float lo, hi;
    asm("mov.b64 {%0, %1}, %2;" : "=f"(lo), "=f"(hi) : "l"(a));
    return lo + hi;
}
__device__ __forceinline__ u32 s2u(const void* p) {
    u32 a;
    asm("{ .reg .u64 t; cvta.to.shared.u64 t, %1; cvt.u32.u64 %0, t; }"
        : "=r"(a) : "l"(p));
    return a;
}
__device__ __forceinline__ void cp_async16(u32 dst, const float* src) {
    asm volatile("cp.async.cg.shared.global [%0], [%1], 16;"
                 :: "r"(dst), "l"(src));
}

// ---------------------------------------------------------------------------
// K0a: pad V rows 500->512, pad c.
// ---------------------------------------------------------------------------
__global__ void k_packV(const float* __restrict__ V,
                        const float* __restrict__ c) {
    int d = blockIdx.x;
    int t = threadIdx.x;
    g_Vp[d*HP + t] = (t < H) ? V[d*H + t] : 0.0f;
    if (d == 0) g_c[t] = (t < H) ? c[t] : 0.0f;
}

// ---------------------------------------------------------------------------
// K0b: tiled transpose W [H,D] -> g_WT [D,HP].
// ---------------------------------------------------------------------------
__global__ void k_packW(const float* __restrict__ W) {
    __shared__ float tile[32][33];
    int d0 = blockIdx.x * 32;
    int h0 = blockIdx.y * 32;
    int tx = threadIdx.x;
    int ty = threadIdx.y;
    #pragma unroll
    for (int i = 0; i < 4; i++) {
        int h = h0 + ty + 8*i;
        int d = d0 + tx;
        float v = 0.0f;
        if (h < H && d < D) v = W[h*D + d];
        tile[ty + 8*i][tx] = v;
    }
    __syncthreads();
    #pragma unroll
    for (int i = 0; i < 4; i++) {
        int d = d0 + ty + 8*i;
        int h = h0 + tx;
        if (d < D) g_WT[d*HP + h] = tile[tx][ty + 8*i];
    }
}

// ---------------------------------------------------------------------------
// K1: partial GEMM. P_s[rows,:] = X[rows, sL:(s+1)L] @ W[sL:(s+1)L, :]
//     Stored at g_A[row][s][:]  (layout [b][s][h]).
// ---------------------------------------------------------------------------
__global__ __launch_bounds__(256)
void k_partial(const float* __restrict__ x) {
    int s  = blockIdx.x;         // 0..26
    int rb = blockIdx.y;         // 0..15
    int t  = threadIdx.x;        // h-pair index
    int rowbase = rb * 32;

    __shared__ u64 sxp[32 * L];
    for (int i = t; i < 32 * L; i += 256) {
        int r = i / L, j = i - r * L;
        sxp[i] = pack2(x[(rowbase + r)*D + s*L + j]);
    }
    __syncthreads();

    u64 acc[32];
    #pragma unroll
    for (int r = 0; r < 32; r++) acc[r] = 0ull;

    const u64* W1 = (const u64*)g_WT;
    #pragma unroll 2
    for (int j = 0; j < L; j++) {
        u64 wv = W1[(size_t)(s*L + j)*256 + t];
        #pragma unroll
        for (int r = 0; r < 32; r++)
            acc[r] = ffma2(sxp[r*L + j], wv, acc[r]);
    }

    u64* A1 = (u64*)g_A;
    #pragma unroll
    for (int r = 0; r < 32; r++)
        A1[((size_t)(rowbase + r)*S + s)*256 + t] = acc[r];
}

// ---------------------------------------------------------------------------
// K2: prefix over segments, one thread per (b,h), in place.
// ---------------------------------------------------------------------------
__global__ __launch_bounds__(256)
void k_prefix() {
    int g = blockIdx.x * 256 + threadIdx.x;
    int h = g & (HP - 1);
    int b = g >> 9;
    float v = g_c[h];
    float* base = g_A + (size_t)b*S*HP + h;
    #pragma unroll
    for (int s = 0; s < S; s++) {
        float p = base[s*HP];
        base[s*HP] = v;
        v += p;
    }
}

// ---------------------------------------------------------------------------
// K3: scan, lane=row layout. Block = (segment s, 32-row tile).
// Warp w owns h in [64w, 64w+64); lane = row; state = 32 u64 regs/lane.
// V/W double-buffered in smem via cp.async (zero register prefetch cost).
// Dot completes in-lane; cross-warp combine + epilogue deferred per chunk.
// Dynamic smem layout (floats):
//   svw   [2][CHS*8*128]  = 2*7168
//   part  [CHS*8*32]      = 1792   ([jj][w][row], coalesced)
//   sx    [32*29]         = 928
//   su    [32*29]         = 928
//   sb    [L]             = 28
//   sl    [32*L]          = 896
//   sxs   [32*L]          = 896
// total 19804 floats = 79216 B
// ---------------------------------------------------------------------------
#define SMEM_SCAN_BYTES (19804*4)

__global__ __launch_bounds__(256, 2)
void k_scan(const float* __restrict__ x,
            const float* __restrict__ u,
            const float* __restrict__ bvec,
            float* __restrict__ out) {
    extern __shared__ __align__(16) float smem[];
    float* svw  = smem;                 // 2*7168
    float* part = svw + 2*7168;         // 1792
    float* sx   = part + 1792;          // 928
    float* su   = sx + 928;             // 928
    float* sb   = su + 928;             // 28
    float* sl   = sb + 28;              // 896
    float* sxs  = sl + 896;             // 896

    int s    = blockIdx.x;       // 0..27
    int rb   = blockIdx.y;       // 0..15
    int tid  = threadIdx.x;
    int w    = tid >> 5;
    int lane = tid & 31;
    int rowbase = rb * 32;

    // Issue chunk-0 prefetch. f = tid + k*256 (float4 units):
    //   q=f&15, gg=f>>4, which=gg&1, gw=gg>>1, w2=gw&7, jj=gw>>3
    // matches dest layout [jj][w][V 64 | W 64].
    {
        int dbase = s*L;
        #pragma unroll
        for (int k = 0; k < CHS; k++) {
            int f = tid + k*256;
            int q = f & 15;
            int gg = f >> 4;
            int which = gg & 1;
            int gw = gg >> 1;
            int w2 = gw & 7;
            int jj = gw >> 3;
            const float* src = (which ? g_WT : g_Vp)
                             + (size_t)(dbase + jj)*HP + w2*64 + q*4;
            cp_async16(s2u(svw) + (u32)(f*16), src);
        }
        asm volatile("cp.async.commit_group;");
    }

    // State init: lane = row, slice [64w, 64w+64).
    u64 a[32];
    {
        const ulonglong2* A2 = (const ulonglong2*)
            (g_A + ((size_t)(rowbase + lane)*S + s)*HP + w*64);
        #pragma unroll
        for (int i = 0; i < 16; i++) {
            ulonglong2 q = A2[i];
            a[2*i] = q.x; a[2*i+1] = q.y;
        }
    }

    // Stage x, u (stride-29 rows) and b.
    for (int i = tid; i < 32*L; i += 256) {
        int r = i / L, j = i - r*L;
        size_t g = (size_t)(rowbase + r)*D + s*L + j;
        sx[r*29 + j] = x[g];
        su[r*29 + j] = u[g];
    }
    if (tid < L) sb[tid] = bvec[s*L + tid];

    asm volatile("cp.async.wait_group 0;");
    __syncthreads();

    for (int c = 0; c < NCH; c++) {
        float* buf = svw + (c & 1)*7168;

        // Prefetch next chunk into the other buffer.
        if (c < NCH-1) {
            float* nbuf = svw + ((c+1) & 1)*7168;
            int dbase = s*L + (c+1)*CHS;
            #pragma unroll
            for (int k = 0; k < CHS; k++) {
                int f = tid + k*256;
                int q = f & 15;
                int gg = f >> 4;
                int which = gg & 1;
                int gw = gg >> 1;
                int w2 = gw & 7;
                int jj = gw >> 3;
                const float* src = (which ? g_WT : g_Vp)
                                 + (size_t)(dbase + jj)*HP + w2*64 + q*4;
                cp_async16(s2u(nbuf) + (u32)(f*16), src);
            }
            asm volatile("cp.async.commit_group;");
        }

        // Compute 7 steps.
        #pragma unroll
        for (int jj = 0; jj < CHS; jj++) {
            int j = c*CHS + jj;
            u64 xx = pack2(sx[lane*29 + j]);
            const ulonglong2* Vb = (const ulonglong2*)(buf + (jj*8 + w)*128);
            const ulonglong2* Wb = Vb + 16;   // +64 floats
            u64 dp0 = 0ull, dp1 = 0ull;
            #pragma unroll
            for (int i = 0; i < 16; i++) {
                ulonglong2 vq = Vb[i];
                ulonglong2 wq = Wb[i];
                dp0 = ffma2(relu2(a[2*i  ]), vq.x, dp0);
                dp1 = ffma2(relu2(a[2*i+1]), vq.y, dp1);
                a[2*i  ] = ffma2(xx, wq.x, a[2*i  ]);
                a[2*i+1] = ffma2(xx, wq.y, a[2*i+1]);
            }
            part[(jj*8 + w)*32 + lane] = hadd2(add2(dp0, dp1));
        }

        __syncthreads();   // part complete; buf fully consumed

        // Reduce across warps + epilogue for this chunk (224 threads).
        if (tid < 32*CHS) {
            int row = tid & 31, jj = tid >> 5;
            float sum = 0.0f;
            #pragma unroll
            for (int w2 = 0; w2 < 8; w2++)
                sum += part[(jj*8 + w2)*32 + row];
            int j = c*CHS + jj;
            float lv = sum + sb[j];
            float uu = su[row*29 + j];
            float e  = expf(-lv);
            float xs = (fmaf(uu, e, uu) < 1.0f) ? 1.0f : 0.0f;
            sl [row*L + j] = lv;
            sxs[row*L + j] = xs;
        }

        asm volatile("cp.async.wait_group 0;");
        __syncthreads();   // part free; next buffer visible
    }

    // Coalesced flush.
    for (int i = tid; i < 32*L; i += 256) {
        int r = i / L, j = i - r*L;
        size_t g = (size_t)(rowbase + r)*D + s*L + j;
        out[g]      = sl[i];
        out[BD + g] = sxs[i];
    }
}

// ---------------------------------------------------------------------------
// Inputs: x[B,D], u[B,D], W[H,D], c[H], V[D,H], b[D]
// Output: [ l (B*D) | x_sample (B*D) ]
// ---------------------------------------------------------------------------
extern "C" void kernel_launch(void* const* d_in, const int* in_sizes, int n_in,
                              void* d_out, int out_size) {
    (void)in_sizes; (void)n_in; (void)out_size;
    const float* x    = (const float*)d_in[0];
    const float* u    = (const float*)d_in[1];
    const float* W    = (const float*)d_in[2];
    const float* c    = (const float*)d_in[3];
    const float* V    = (const float*)d_in[4];
    const float* bvec = (const float*)d_in[5];
    float* out = (float*)d_out;

    cudaFuncSetAttribute(k_scan, cudaFuncAttributeMaxDynamicSharedMemorySize,
                         SMEM_SCAN_BYTES);

    k_packV  <<<D, HP>>>(V, c);
    k_packW  <<<dim3((D+31)/32, HP/32), dim3(32, 8)>>>(W);
    k_partial<<<dim3(S-1, B/32), 256>>>(x);
    k_prefix <<<(B*HP)/256, 256>>>();
    k_scan   <<<dim3(S, B/32), 256, SMEM_SCAN_BYTES>>>(x, u, bvec, out);
}

// round 11
// speedup vs baseline: 1.0480x; 1.0045x over previous
#include <cuda_runtime.h>
#include <cstdint>
#include <math.h>

// Problem constants
#define D   784
#define H   500
#define HP  512
#define B   512
#define S   28           // segments (784 = 28*28)
#define L   28           // steps per segment
#define BD  (B*D)
#define CHS 7            // steps per chunk in k_scan
#define NCH 4            // chunks (4*7 = 28)
#define TPB 512          // k_scan threads (16 warps)

typedef unsigned long long u64;
typedef unsigned int u32;

// Static device scratch
__device__ float g_WT[D*HP];     // W^T padded: [d][h]
__device__ float g_Vp[D*HP];     // V padded:   [d][h]
__device__ float g_c [HP];
__device__ float g_A [B*S*HP];   // partials then checkpoints: [b][s][h]

// ---- packed f32x2 helpers -------------------------------------------------
__device__ __forceinline__ u64 ffma2(u64 a, u64 b, u64 c) {
    u64 d;
    asm("fma.rn.f32x2 %0, %1, %2, %3;" : "=l"(d) : "l"(a), "l"(b), "l"(c));
    return d;
}
__device__ __forceinline__ u64 add2(u64 a, u64 b) {
    u64 d;
    asm("add.rn.f32x2 %0, %1, %2;" : "=l"(d) : "l"(a), "l"(b));
    return d;
}
__device__ __forceinline__ u64 relu2(u64 a) {
    u64 r;
    asm("{\n\t.reg .f32 lo, hi;\n\t"
        "mov.b64 {lo, hi}, %1;\n\t"
        "max.f32 lo, lo, 0f00000000;\n\t"
        "max.f32 hi, hi, 0f00000000;\n\t"
        "mov.b64 %0, {lo, hi};\n\t}" : "=l"(r) : "l"(a));
    return r;
}
__device__ __forceinline__ u64 pack2(float x) {
    u64 r;
    asm("mov.b64 %0, {%1, %1};" : "=l"(r) : "f"(x));
    return r;
}
__device__ __forceinline__ float hadd2(u64 a) {
    float lo, hi;
    asm("mov.b64 {%0, %1}, %2;" : "=f"(lo), "=f"(hi) : "l"(a));
    return lo + hi;
}
__device__ __forceinline__ u32 s2u(const void* p) {
    u32 a;
    asm("{ .reg .u64 t; cvta.to.shared.u64 t, %1; cvt.u32.u64 %0, t; }"
        : "=r"(a) : "l"(p));
    return a;
}
__device__ __forceinline__ void cp_async16(u32 dst, const float* src) {
    asm volatile("cp.async.cg.shared.global [%0], [%1], 16;"
                 :: "r"(dst), "l"(src));
}

// ---------------------------------------------------------------------------
// K0a: pad V rows 500->512, pad c.
// ---------------------------------------------------------------------------
__global__ void k_packV(const float* __restrict__ V,
                        const float* __restrict__ c) {
    int d = blockIdx.x;
    int t = threadIdx.x;
    g_Vp[d*HP + t] = (t < H) ? V[d*H + t] : 0.0f;
    if (d == 0) g_c[t] = (t < H) ? c[t] : 0.0f;
}

// ---------------------------------------------------------------------------
// K0b: tiled transpose W [H,D] -> g_WT [D,HP].
// ---------------------------------------------------------------------------
__global__ void k_packW(const float* __restrict__ W) {
    __shared__ float tile[32][33];
    int d0 = blockIdx.x * 32;
    int h0 = blockIdx.y * 32;
    int tx = threadIdx.x;
    int ty = threadIdx.y;
    #pragma unroll
    for (int i = 0; i < 4; i++) {
        int h = h0 + ty + 8*i;
        int d = d0 + tx;
        float v = 0.0f;
        if (h < H && d < D) v = W[h*D + d];
        tile[ty + 8*i][tx] = v;
    }
    __syncthreads();
    #pragma unroll
    for (int i = 0; i < 4; i++) {
        int d = d0 + ty + 8*i;
        int h = h0 + tx;
        if (d < D) g_WT[d*HP + h] = tile[tx][ty + 8*i];
    }
}

// ---------------------------------------------------------------------------
// K1: partial GEMM. P_s[rows,:] = X[rows, sL:(s+1)L] @ W[sL:(s+1)L, :]
//     Stored at g_A[row][s][:]  (layout [b][s][h]).
// ---------------------------------------------------------------------------
__global__ __launch_bounds__(256)
void k_partial(const float* __restrict__ x) {
    int s  = blockIdx.x;         // 0..26
    int rb = blockIdx.y;         // 0..15
    int t  = threadIdx.x;        // h-pair index
    int rowbase = rb * 32;

    __shared__ u64 sxp[32 * L];
    for (int i = t; i < 32 * L; i += 256) {
        int r = i / L, j = i - r * L;
        sxp[i] = pack2(x[(rowbase + r)*D + s*L + j]);
    }
    __syncthreads();

    u64 acc[32];
    #pragma unroll
    for (int r = 0; r < 32; r++) acc[r] = 0ull;

    const u64* W1 = (const u64*)g_WT;
    #pragma unroll 2
    for (int j = 0; j < L; j++) {
        u64 wv = W1[(size_t)(s*L + j)*256 + t];
        #pragma unroll
        for (int r = 0; r < 32; r++)
            acc[r] = ffma2(sxp[r*L + j], wv, acc[r]);
    }

    u64* A1 = (u64*)g_A;
    #pragma unroll
    for (int r = 0; r < 32; r++)
        A1[((size_t)(rowbase + r)*S + s)*256 + t] = acc[r];
}

// ---------------------------------------------------------------------------
// K2: prefix over segments, one thread per (b,h), in place.
//     All 28 loads issued up front (explicit register array -> MLP=28).
// ---------------------------------------------------------------------------
__global__ __launch_bounds__(256)
void k_prefix() {
    int g = blockIdx.x * 256 + threadIdx.x;
    int h = g & (HP - 1);
    int b = g >> 9;
    float* base = g_A + (size_t)b*S*HP + h;
    float p[S];
    #pragma unroll
    for (int s = 0; s < S; s++) p[s] = base[s*HP];
    float v = g_c[h];
    #pragma unroll
    for (int s = 0; s < S; s++) {
        float t = p[s];
        base[s*HP] = v;
        v += t;
    }
}

// ---------------------------------------------------------------------------
// K3: scan, lane=row layout, 16 warps. Block = (segment s, 32-row tile).
// Warp w owns h in [32w, 32w+32); lane = row; state = 16 u64 regs/lane.
// V/W double-buffered in smem via cp.async; dot completes in-lane; cross-warp
// combine + epilogue deferred per chunk.
// Dynamic smem (floats):
//   svw [2][CHS*16*64] = 2*7168 | part [CHS*16*32] = 3584 | sx 928 | su 928
//   sb 28 | sl 896 | sxs 896   -> total 21596 floats = 86384 B
// ---------------------------------------------------------------------------
#define SMEM_SCAN_BYTES (21596*4)

__global__ __launch_bounds__(TPB, 2)
void k_scan(const float* __restrict__ x,
            const float* __restrict__ u,
            const float* __restrict__ bvec,
            float* __restrict__ out) {
    extern __shared__ __align__(16) float smem[];
    float* svw  = smem;                 // 2*7168
    float* part = svw + 2*7168;         // 3584
    float* sx   = part + 3584;          // 928
    float* su   = sx + 928;             // 928
    float* sb   = su + 928;             // 28
    float* sl   = sb + 28;              // 896
    float* sxs  = sl + 896;             // 896

    int s    = blockIdx.x;       // 0..27
    int rb   = blockIdx.y;       // 0..15
    int tid  = threadIdx.x;
    int w    = tid >> 5;         // 0..15
    int lane = tid & 31;
    int rowbase = rb * 32;

    // Chunk loader: f = float4 index 0..1791.
    // f = jj*256 + w2*16 + which*8 + q  (layout [jj][w2][V 32 | W 32])
    // Issue chunk-0 prefetch.
    {
        int dbase = s*L;
        #pragma unroll
        for (int k = 0; k < 4; k++) {
            int f = tid + k*TPB;
            if (f < 1792) {
                int q = f & 7;
                int gg = f >> 3;
                int which = gg & 1;
                int gw = gg >> 1;
                int w2 = gw & 15;
                int jj = gw >> 4;
                const float* src = (which ? g_WT : g_Vp)
                                 + (size_t)(dbase + jj)*HP + w2*32 + q*4;
                cp_async16(s2u(svw) + (u32)(f*16), src);
            }
        }
        asm volatile("cp.async.commit_group;");
    }

    // State init: lane = row, slice [32w, 32w+32).
    u64 a[16];
    {
        const ulonglong2* A2 = (const ulonglong2*)
            (g_A + ((size_t)(rowbase + lane)*S + s)*HP + w*32);
        #pragma unroll
        for (int i = 0; i < 8; i++) {
            ulonglong2 q = A2[i];
            a[2*i] = q.x; a[2*i+1] = q.y;
        }
    }

    // Stage x, u (stride-29 rows) and b.
    for (int i = tid; i < 32*L; i += TPB) {
        int r = i / L, j = i - r*L;
        size_t g = (size_t)(rowbase + r)*D + s*L + j;
        sx[r*29 + j] = x[g];
        su[r*29 + j] = u[g];
    }
    if (tid < L) sb[tid] = bvec[s*L + tid];

    asm volatile("cp.async.wait_group 0;");
    __syncthreads();

    for (int c = 0; c < NCH; c++) {
        float* buf = svw + (c & 1)*7168;

        // Prefetch next chunk into the other buffer.
        if (c < NCH-1) {
            float* nbuf = svw + ((c+1) & 1)*7168;
            int dbase = s*L + (c+1)*CHS;
            #pragma unroll
            for (int k = 0; k < 4; k++) {
                int f = tid + k*TPB;
                if (f < 1792) {
                    int q = f & 7;
                    int gg = f >> 3;
                    int which = gg & 1;
                    int gw = gg >> 1;
                    int w2 = gw & 15;
                    int jj = gw >> 4;
                    const float* src = (which ? g_WT : g_Vp)
                                     + (size_t)(dbase + jj)*HP + w2*32 + q*4;
                    cp_async16(s2u(nbuf) + (u32)(f*16), src);
                }
            }
            asm volatile("cp.async.commit_group;");
        }

        // Compute 7 steps.
        #pragma unroll 1
        for (int jj = 0; jj < CHS; jj++) {
            int j = c*CHS + jj;
            u64 xx = pack2(sx[lane*29 + j]);
            const ulonglong2* Vb = (const ulonglong2*)(buf + (jj*16 + w)*64);
            const ulonglong2* Wb = Vb + 8;   // +32 floats
            u64 dp0 = 0ull, dp1 = 0ull;
            #pragma unroll
            for (int i = 0; i < 8; i++) {
                ulonglong2 vq = Vb[i];
                ulonglong2 wq = Wb[i];
                dp0 = ffma2(relu2(a[2*i  ]), vq.x, dp0);
                dp1 = ffma2(relu2(a[2*i+1]), vq.y, dp1);
                a[2*i  ] = ffma2(xx, wq.x, a[2*i  ]);
                a[2*i+1] = ffma2(xx, wq.y, a[2*i+1]);
            }
            part[(jj*16 + w)*32 + lane] = hadd2(add2(dp0, dp1));
        }

        __syncthreads();   // part complete; buf fully consumed

        // Reduce across 16 warps + epilogue for this chunk (224 threads).
        if (tid < 32*CHS) {
            int row = tid & 31, jj = tid >> 5;
            float sum = 0.0f;
            #pragma unroll
            for (int w2 = 0; w2 < 16; w2++)
                sum += part[(jj*16 + w2)*32 + row];
            int j = c*CHS + jj;
            float lv = sum + sb[j];
            float uu = su[row*29 + j];
            float e  = expf(-lv);
            float xs = (fmaf(uu, e, uu) < 1.0f) ? 1.0f : 0.0f;
            sl [row*L + j] = lv;
            sxs[row*L + j] = xs;
        }

        asm volatile("cp.async.wait_group 0;");
        __syncthreads();   // part free; next buffer visible
    }

    // Coalesced flush.
    for (int i = tid; i < 32*L; i += TPB) {
        int r = i / L, j = i - r*L;
        size_t g = (size_t)(rowbase + r)*D + s*L + j;
        out[g]      = sl[i];
        out[BD + g] = sxs[i];
    }
}

// ---------------------------------------------------------------------------
// Inputs: x[B,D], u[B,D], W[H,D], c[H], V[D,H], b[D]
// Output: [ l (B*D) | x_sample (B*D) ]
// ---------------------------------------------------------------------------
extern "C" void kernel_launch(void* const* d_in, const int* in_sizes, int n_in,
                              void* d_out, int out_size) {
    (void)in_sizes; (void)n_in; (void)out_size;
    const float* x    = (const float*)d_in[0];
    const float* u    = (const float*)d_in[1];
    const float* W    = (const float*)d_in[2];
    const float* c    = (const float*)d_in[3];
    const float* V    = (const float*)d_in[4];
    const float* bvec = (const float*)d_in[5];
    float* out = (float*)d_out;

    cudaFuncSetAttribute(k_scan, cudaFuncAttributeMaxDynamicSharedMemorySize,
                         SMEM_SCAN_BYTES);

    k_packV  <<<D, HP>>>(V, c);
    k_packW  <<<dim3((D+31)/32, HP/32), dim3(32, 8)>>>(W);
    k_partial<<<dim3(S-1, B/32), 256>>>(x);
    k_prefix <<<(B*HP)/256, 256>>>();
    k_scan   <<<dim3(S, B/32), TPB, SMEM_SCAN_BYTES>>>(x, u, bvec, out);
}